// round 10
// baseline (speedup 1.0000x reference)
#include <cuda_runtime.h>
#include <cuda_fp16.h>
#include <cstdint>

#define BATCH     512
#define SIZE_IN   1024
#define SIZE_OUT  256
#define NQ        16

#define BT        64                 // batch tile per CTA
#define ISPLIT    37                 // 8 * 37 = 296 = 148 SMs * 2 CTAs exactly
#define ICHUNKMAX 28                 // ceil(1024/37)
#define NTHREADS  512
#define QSTRIDE   (SIZE_IN * SIZE_OUT)   // 262144: halves per q-plane

// fp16 copy of the weight table (8 MB static scratch; no allocation allowed)
__device__ __half g_tableh[NQ * SIZE_IN * SIZE_OUT];

// out[b,o] = bias[o]  (atomic accumulation target)
__global__ void il_init_out(const float* __restrict__ bias, float* __restrict__ out) {
    int i = blockIdx.x * blockDim.x + threadIdx.x;
    if (i < BATCH * SIZE_OUT) out[i] = bias[i & (SIZE_OUT - 1)];
}

// table fp32 -> fp16, 16 elems/thread, 4 front-batched LDG.128 for MLP
__global__ void il_prep_half(const float* __restrict__ table) {
    const size_t i = ((size_t)blockIdx.x * blockDim.x + threadIdx.x) * 16;
    float4 a0 = *reinterpret_cast<const float4*>(table + i);
    float4 a1 = *reinterpret_cast<const float4*>(table + i + 4);
    float4 a2 = *reinterpret_cast<const float4*>(table + i + 8);
    float4 a3 = *reinterpret_cast<const float4*>(table + i + 12);
    __half2 h[8];
    h[0] = __floats2half2_rn(a0.x, a0.y); h[1] = __floats2half2_rn(a0.z, a0.w);
    h[2] = __floats2half2_rn(a1.x, a1.y); h[3] = __floats2half2_rn(a1.z, a1.w);
    h[4] = __floats2half2_rn(a2.x, a2.y); h[5] = __floats2half2_rn(a2.z, a2.w);
    h[6] = __floats2half2_rn(a3.x, a3.y); h[7] = __floats2half2_rn(a3.z, a3.w);
    *reinterpret_cast<uint4*>(g_tableh + i)     = *reinterpret_cast<uint4*>(h);
    *reinterpret_cast<uint4*>(g_tableh + i + 8) = *reinterpret_cast<uint4*>(h + 4);
}

// One CTA: 64 batches x (27..28) features x 256 outputs.
// No weight staging: coalesced LDG.128 straight from the L2-resident fp16 table,
// L1 caches the 16 candidate rows per feature. No barriers in the main loop.
__global__ __launch_bounds__(NTHREADS, 2)
void il_main(const float* __restrict__ x,
             const int* __restrict__ indices,   // JAX canonicalizes int64 -> int32
             float* __restrict__ out) {
    const int b0  = blockIdx.x * BT;
    const int lo  = (int)(((long long)blockIdx.y * SIZE_IN) / ISPLIT);
    const int hi  = (int)(((long long)(blockIdx.y + 1) * SIZE_IN) / ISPLIT);
    const int len = hi - lo;             // 27 or 28
    const int t   = threadIdx.x;
    const int og  = t & 31;              // output columns og*8 .. og*8+7
    const int bg  = t >> 5;              // batches bg*4 .. bg*4+3 (warp-uniform)

    __shared__ float2 sxq[BT][ICHUNKMAX];   // {x, float-bits of q * QSTRIDE}

    // Preload x and quantile plane-offsets for the (64 batch x len) tile.
    {
        const int bl    = t >> 3;        // 0..63
        const int lane8 = t & 7;
        const float* xp = x       + (size_t)(b0 + bl) * SIZE_IN + lo;
        const int*   qp = indices + (size_t)(b0 + bl) * SIZE_IN + lo;
        #pragma unroll
        for (int k = 0; k < 4; k++) {
            const int ii = lane8 + k * 8;
            if (ii < len)
                sxq[bl][ii] = make_float2(xp[ii], __int_as_float(qp[ii] * QSTRIDE));
        }
    }
    __syncthreads();   // the only block barrier

    float acc[4][8];
    #pragma unroll
    for (int bl = 0; bl < 4; bl++)
        #pragma unroll
        for (int c = 0; c < 8; c++) acc[bl][c] = 0.f;

    const __half* wbase = g_tableh + og * 8;

    #pragma unroll 2
    for (int ii = 0; ii < len; ii++) {
        const int icol = (lo + ii) * SIZE_OUT;   // uniform
        float xs[4]; const __half* wp[4];
        #pragma unroll
        for (int bl = 0; bl < 4; bl++) {
            const float2 v = sxq[bg * 4 + bl][ii];   // LDS broadcast
            xs[bl] = v.x;
            wp[bl] = wbase + __float_as_int(v.y) + icol;
        }
        uint4 u[4];
        #pragma unroll
        for (int bl = 0; bl < 4; bl++)                // 4 outstanding LDG.128
            u[bl] = *reinterpret_cast<const uint4*>(wp[bl]);
        #pragma unroll
        for (int bl = 0; bl < 4; bl++) {
            const __half2* hp = reinterpret_cast<const __half2*>(&u[bl]);
            #pragma unroll
            for (int p = 0; p < 4; p++) {
                const float2 f = __half22float2(hp[p]);
                acc[bl][p * 2 + 0] += xs[bl] * f.x;
                acc[bl][p * 2 + 1] += xs[bl] * f.y;
            }
        }
    }

    // Combine split-k partials (coalesced REDG across lanes).
    #pragma unroll
    for (int bl = 0; bl < 4; bl++) {
        const int b = b0 + bg * 4 + bl;
        float* op = out + (size_t)b * SIZE_OUT + og * 8;
        #pragma unroll
        for (int c = 0; c < 8; c++) atomicAdd(op + c, acc[bl][c]);
    }
}

extern "C" void kernel_launch(void* const* d_in, const int* in_sizes, int n_in,
                              void* d_out, int out_size) {
    const float* x       = (const float*)d_in[0];
    const int*   indices = (const int*)d_in[1];
    const float* table   = (const float*)d_in[2];
    const float* bias    = (const float*)d_in[3];
    float*       out     = (float*)d_out;

    // table -> fp16: 4,194,304 elems / 16 per thread / 256 per block = 1024 blocks
    il_prep_half<<<1024, 256>>>(table);

    il_init_out<<<(BATCH * SIZE_OUT + 255) / 256, 256>>>(bias, out);

    dim3 grid(BATCH / BT, ISPLIT);   // 8 x 37 = 296 CTAs = 148 SMs * 2
    il_main<<<grid, NTHREADS>>>(x, indices, out);
}

// round 11
// speedup vs baseline: 1.2361x; 1.2361x over previous
#include <cuda_runtime.h>
#include <cuda_fp16.h>
#include <cstdint>

#define BATCH     512
#define SIZE_IN   1024
#define SIZE_OUT  256
#define NQ        16

#define BT        64                 // batch tile per CTA
#define ISPLIT    37                 // 8 * 37 = 296 = 148 SMs * 2 CTAs exactly
#define NPHMAX    14                 // ceil(28/2)
#define NTHREADS  512

// fp16 copy of the weight table (8 MB static scratch; no allocation allowed)
__device__ __half g_tableh[NQ * SIZE_IN * SIZE_OUT];

// out[b,o] = bias[o]  (atomic accumulation target)
__global__ void il_init_out(const float* __restrict__ bias, float* __restrict__ out) {
    int i = blockIdx.x * blockDim.x + threadIdx.x;
    if (i < BATCH * SIZE_OUT) out[i] = bias[i & (SIZE_OUT - 1)];
}

// table fp32 -> fp16, 8 elements per thread (32B read / 16B write, coalesced)
__global__ void il_prep_half(const float* __restrict__ table) {
    const size_t i = ((size_t)blockIdx.x * blockDim.x + threadIdx.x) * 8;
    const float4 a = *reinterpret_cast<const float4*>(table + i);
    const float4 b = *reinterpret_cast<const float4*>(table + i + 4);
    __half2 h[4];
    h[0] = __floats2half2_rn(a.x, a.y);
    h[1] = __floats2half2_rn(a.z, a.w);
    h[2] = __floats2half2_rn(b.x, b.y);
    h[3] = __floats2half2_rn(b.z, b.w);
    *reinterpret_cast<uint4*>(g_tableh + i) = *reinterpret_cast<uint4*>(h);
}

__device__ __forceinline__ void cp_async16(uint32_t saddr, const void* gptr) {
    asm volatile("cp.async.cg.shared.global [%0], [%1], 16;\n" :: "r"(saddr), "l"(gptr));
}
__device__ __forceinline__ void cp_commit() {
    asm volatile("cp.async.commit_group;\n" ::: "memory");
}
__device__ __forceinline__ void cp_wait0() {
    asm volatile("cp.async.wait_group 0;\n" ::: "memory");
}
__device__ __forceinline__ void red_v4(float* p, float a, float b, float c, float d) {
    asm volatile("red.global.add.v4.f32 [%0], {%1, %2, %3, %4};"
                 :: "l"(p), "f"(a), "f"(b), "f"(c), "f"(d) : "memory");
}

// One CTA: 64 batches x (27..28) features x 256 outputs.
// Phases of 2 features: double-buffered 16 KB fp16 stage via cp.async,
// one float4 broadcast carries both features' {x, q-offset} per batch.
__global__ __launch_bounds__(NTHREADS, 2)
void il_main(const float* __restrict__ x,
             const int* __restrict__ indices,   // JAX canonicalizes int64 -> int32
             float* __restrict__ out) {
    const int b0  = blockIdx.x * BT;
    const int lo  = (int)(((long long)blockIdx.y * SIZE_IN) / ISPLIT);
    const int hi  = (int)(((long long)(blockIdx.y + 1) * SIZE_IN) / ISPLIT);
    const int len = hi - lo;             // 27 or 28
    const int nph = (len + 1) >> 1;      // 14
    const int t   = threadIdx.x;
    const int og  = t & 31;              // output columns og*8 .. og*8+7
    const int bg  = t >> 5;              // batches bg*4 .. bg*4+3 (warp-uniform)

    // Stage layout (halves): buf*8192 + feat*4096 + q*256 + col
    __shared__ __align__(16) __half sW[2 * 2 * NQ * SIZE_OUT];   // 32 KB
    __shared__ float4 sxq[BT][NPHMAX];   // {x0, bits(q0*256), x1, bits(q1*256)}

    const uint32_t sW_u32 = (uint32_t)__cvta_generic_to_shared(sW);
    const int sq = t >> 5;               // staged row 0..15
    const int sc = t & 31;               // 16B chunk 0..31 within the 512B row

    // Preload sxq: thread covers batch bl = t>>3, phases (t&7) + 8k.
    {
        const int bl = t >> 3;
        const float* xp = x       + (size_t)(b0 + bl) * SIZE_IN;
        const int*   qp = indices + (size_t)(b0 + bl) * SIZE_IN;
        #pragma unroll
        for (int k = 0; k < 2; k++) {
            const int p = (t & 7) + k * 8;
            if (p < nph) {
                const int i0 = lo + 2 * p;
                float4 v;
                v.x = xp[i0];
                v.y = __int_as_float(qp[i0] * SIZE_OUT);
                if (i0 + 1 < hi) {
                    v.z = xp[i0 + 1];
                    v.w = __int_as_float(qp[i0 + 1] * SIZE_OUT);
                } else {
                    v.z = 0.f;
                    v.w = __int_as_float(0);
                }
                sxq[bl][p] = v;
            }
        }
    }

    float acc[4][8];
    #pragma unroll
    for (int bl = 0; bl < 4; bl++)
        #pragma unroll
        for (int c = 0; c < 8; c++) acc[bl][c] = 0.f;

    // Prefetch phase 0 into buffer 0 (2 cp.async16 per thread).
    {
        const __half* src0 = g_tableh + ((size_t)sq * SIZE_IN + lo) * SIZE_OUT + sc * 8;
        cp_async16(sW_u32 + (uint32_t)(sq * 512 + sc * 16), src0);
        cp_async16(sW_u32 + (uint32_t)(4096 * 2 + sq * 512 + sc * 16), src0 + SIZE_OUT);
        cp_commit();
    }

    for (int p = 0; p < nph; p++) {
        const int buf = p & 1;

        cp_wait0();
        __syncthreads();   // staged data visible; everyone done reading buf^1

        if (p + 1 < nph) {
            const int i0 = lo + 2 * (p + 1);
            const uint32_t dst = sW_u32 + (uint32_t)((buf ^ 1) * 16384 + sq * 512 + sc * 16);
            const __half* src = g_tableh + ((size_t)sq * SIZE_IN + i0) * SIZE_OUT + sc * 8;
            cp_async16(dst, src);
            if (i0 + 1 < hi) cp_async16(dst + 8192u, src + SIZE_OUT);
            cp_commit();
        }

        const __half* wb  = sW + buf * 8192;
        const bool    two = (2 * p + 1 < len);

        float4 v[4];
        #pragma unroll
        for (int bl = 0; bl < 4; bl++) v[bl] = sxq[bg * 4 + bl][p];   // 16B broadcast

        // feature 0 of the phase
        #pragma unroll
        for (int bl = 0; bl < 4; bl++) {
            const uint4 u = *reinterpret_cast<const uint4*>(
                wb + __float_as_int(v[bl].y) + og * 8);
            const __half2* hp = reinterpret_cast<const __half2*>(&u);
            #pragma unroll
            for (int q = 0; q < 4; q++) {
                const float2 f = __half22float2(hp[q]);
                acc[bl][q * 2 + 0] += v[bl].x * f.x;
                acc[bl][q * 2 + 1] += v[bl].x * f.y;
            }
        }
        // feature 1 of the phase
        if (two) {
            #pragma unroll
            for (int bl = 0; bl < 4; bl++) {
                const uint4 u = *reinterpret_cast<const uint4*>(
                    wb + 4096 + __float_as_int(v[bl].w) + og * 8);
                const __half2* hp = reinterpret_cast<const __half2*>(&u);
                #pragma unroll
                for (int q = 0; q < 4; q++) {
                    const float2 f = __half22float2(hp[q]);
                    acc[bl][q * 2 + 0] += v[bl].z * f.x;
                    acc[bl][q * 2 + 1] += v[bl].z * f.y;
                }
            }
        }
    }

    // Combine split-k partials: 2 vectorized reductions per batch.
    #pragma unroll
    for (int bl = 0; bl < 4; bl++) {
        const int b = b0 + bg * 4 + bl;
        float* op = out + (size_t)b * SIZE_OUT + og * 8;
        red_v4(op,     acc[bl][0], acc[bl][1], acc[bl][2], acc[bl][3]);
        red_v4(op + 4, acc[bl][4], acc[bl][5], acc[bl][6], acc[bl][7]);
    }
}

extern "C" void kernel_launch(void* const* d_in, const int* in_sizes, int n_in,
                              void* d_out, int out_size) {
    const float* x       = (const float*)d_in[0];
    const int*   indices = (const int*)d_in[1];
    const float* table   = (const float*)d_in[2];
    const float* bias    = (const float*)d_in[3];
    float*       out     = (float*)d_out;

    il_init_out<<<(BATCH * SIZE_OUT + 255) / 256, 256>>>(bias, out);

    // table -> fp16: 4,194,304 elems / 8 per thread / 256 per block = 2048 blocks
    il_prep_half<<<2048, 256>>>(table);

    dim3 grid(BATCH / BT, ISPLIT);   // 8 x 37 = 296 CTAs = 148 SMs * 2
    il_main<<<grid, NTHREADS>>>(x, indices, out);
}